// round 10
// baseline (speedup 1.0000x reference)
#include <cuda_runtime.h>
#include <cuda_fp16.h>
#include <cstdint>

// ============================================================================
// MultiHeadGraphAttentionLayer — reduced form.
// softmax rows sum to 1, so out = hp = h @ Wcat : [16384,256] x [256,256].
// Prepass: h fp32->fp16 + swizzled fp16 B images of Wcat^T.
// GEMM: 512 threads / 16 warps per CTA (warp tile 32x32, acc=32 regs) for
// 2x resident warps; triple-buffered fp16 A slabs via cp.async; verbatim B
// image copy. ldmatrix + mma.sync.m16n8k16. sm_103 base ISA only.
// ============================================================================

static constexpr int M_TOTAL = 16384;
static constexpr int N_OUT   = 256;
static constexpr int K_DIM   = 256;

static constexpr int CTA_M   = 128;
static constexpr int CTA_N   = 128;
static constexpr int THREADS = 512;

static constexpr int KSLAB   = 64;
static constexpr int NSLICE  = K_DIM / KSLAB;   // 4

static constexpr int B_IMG_HALVES = CTA_N * K_DIM;          // 32768 (64 KB)
static constexpr int B_CHUNK_B    = 16384;                  // one k-group of 4 k-steps
static constexpr int A_SLAB_BYTES = CTA_M * KSLAB * 2;      // 16384
static constexpr int SMEM_BYTES   = B_IMG_HALVES * 2 + 3 * A_SLAB_BYTES; // 114688

// static device scratch (no allocation): fp16 h + two swizzled B images
__device__ __align__(16) __half g_hhalf[(size_t)M_TOTAL * K_DIM];   // 8 MB
__device__ __align__(16) __half g_bt[2 * B_IMG_HALVES];             // 128 KB

__device__ __forceinline__ uint32_t smem_u32(const void* p) {
    uint32_t a;
    asm("{ .reg .u64 t; cvta.to.shared.u64 t, %1; cvt.u32.u64 %0, t; }"
        : "=r"(a) : "l"(p));
    return a;
}

__device__ __forceinline__ void ldm_x4(uint32_t* r, uint32_t addr) {
    asm volatile("ldmatrix.sync.aligned.m8n8.x4.shared.b16 {%0,%1,%2,%3}, [%4];"
                 : "=r"(r[0]), "=r"(r[1]), "=r"(r[2]), "=r"(r[3])
                 : "r"(addr));
}

__device__ __forceinline__ void mma16816(float* c, const uint32_t* a,
                                         const uint32_t* b) {
    asm volatile(
        "mma.sync.aligned.m16n8k16.row.col.f32.f16.f16.f32 "
        "{%0,%1,%2,%3}, {%4,%5,%6,%7}, {%8,%9}, {%0,%1,%2,%3};"
        : "+f"(c[0]), "+f"(c[1]), "+f"(c[2]), "+f"(c[3])
        : "r"(a[0]), "r"(a[1]), "r"(a[2]), "r"(a[3]), "r"(b[0]), "r"(b[1]));
}

#define CP_ASYNC_16(smem_addr, gptr)                                           \
    asm volatile("cp.async.cg.shared.global [%0], [%1], 16;"                   \
                 :: "r"(smem_addr), "l"(gptr))
#define CP_ASYNC_COMMIT() asm volatile("cp.async.commit_group;")
#define CP_ASYNC_WAIT(n)  asm volatile("cp.async.wait_group %0;" :: "n"(n))

// B image byte offset for local row c (0..127), col f (0..255):
// blocked SW128 atoms: atom = (c>>3) + (f>>6)*16, 1024 B each.
__device__ __forceinline__ uint32_t b_img_off(int c, int f) {
    uint32_t off = (uint32_t)(((c >> 3) + (f >> 6) * 16) * 1024
                              + (c & 7) * 128 + (f & 63) * 2);
    return off ^ ((off >> 3) & 0x70);
}

// ---------------- prepass: h fp32->fp16 + B images ----------------
__global__ __launch_bounds__(512)
void prep_kernel(const float4* __restrict__ h4, const float* __restrict__ W) {
    const int n4 = M_TOTAL * K_DIM / 4;   // 1048576
    int t = blockIdx.x * blockDim.x + threadIdx.x;
    if (t < n4) {
        float4 v = h4[t];
        __half2 p0 = __floats2half2_rn(v.x, v.y);
        __half2 p1 = __floats2half2_rn(v.z, v.w);
        uint2 u;
        u.x = *reinterpret_cast<uint32_t*>(&p0);
        u.y = *reinterpret_cast<uint32_t*>(&p1);
        reinterpret_cast<uint2*>(g_hhalf)[t] = u;
    } else {
        int u = t - n4;                  // 0..65535 -> B images
        if (u < 2 * B_IMG_HALVES) {
            int img = u >> 15;
            int rem = u & 32767;
            int f   = rem >> 7;          // 0..255
            int c   = rem & 127;         // local col (consecutive -> coalesced d)
            int n   = img * 128 + c;
            int hh  = n >> 6;
            int d   = n & 63;
            float w = W[hh * 16384 + f * 64 + d];
            g_bt[img * B_IMG_HALVES + (b_img_off(c, f) >> 1)] = __float2half_rn(w);
        }
    }
}

// ---------------- GEMM ----------------
__global__ __launch_bounds__(THREADS, 2)
void gat_gemm_kernel(float* __restrict__ out) {
    extern __shared__ __half smem[];
    __half* Bs = smem;                        // 64 KB swizzled image
    __half* As = smem + B_IMG_HALVES;         // 3 x 16 KB slabs

    const int tid  = threadIdx.x;
    const int wid  = tid >> 5;
    const int lane = tid & 31;

    const int bm   = blockIdx.x >> 1;
    const int img  = blockIdx.x & 1;
    const int bn   = img * CTA_N;
    const long arow0 = (long)bm * CTA_M;

    const __half* aGlob = g_hhalf + arow0 * K_DIM;
    const __half* bGlob = g_bt + img * B_IMG_HALVES;
    const uint32_t BsU = smem_u32(Bs);
    const uint32_t AsU = smem_u32(As);

    // A slab: 1024 x 16B chunks, SW128-swizzled 128 B rows (2 chunks/thread)
    #define ISSUE_A(slice, buf) do {                                           \
        const __half* _src = aGlob + (slice) * KSLAB;                          \
        _Pragma("unroll")                                                      \
        for (int i = 0; i < 2; i++) {                                          \
            int c   = tid + i * THREADS;                                       \
            int r   = c >> 3;                                                  \
            int c8  = c & 7;                                                   \
            uint32_t dst = AsU + (uint32_t)((buf) * A_SLAB_BYTES + r * 128     \
                                            + ((c8 * 16) ^ ((r & 7) << 4)));  \
            CP_ASYNC_16(dst, _src + r * K_DIM + c8 * 8);                       \
        }                                                                      \
    } while (0)

    // head: G0 = {B image verbatim, A slab 0}, G1 = {A slab 1}
    {
        #pragma unroll
        for (int i = 0; i < 8; i++) {
            int c = tid + i * THREADS;
            CP_ASYNC_16(BsU + (uint32_t)(c * 16), bGlob + c * 8);
        }
    }
    ISSUE_A(0, 0); CP_ASYNC_COMMIT();
    ISSUE_A(1, 1); CP_ASYNC_COMMIT();

    // ---- warp tiling: 16 warps = 4(m) x 4(n); warp tile 32(m) x 32(n) ----
    const int wm = wid & 3;
    const int wn = wid >> 2;       // 0..3

    float acc[2][4][4];
    #pragma unroll
    for (int mt = 0; mt < 2; mt++)
        #pragma unroll
        for (int nt = 0; nt < 4; nt++)
            #pragma unroll
            for (int q = 0; q < 4; q++) acc[mt][nt][q] = 0.f;

    // A lane addressing (verified R5 form)
    const int arl   = wm * 32 + (lane & 15);
    const uint32_t aXor  = (uint32_t)((arl & 7) << 4);
    const uint32_t aRowB = (uint32_t)(arl * 128);
    const int akl = (lane >> 4) * 8;

    // B lane addressing: warp covers n in [wn*32, wn*32+32) -> 2 x 16-row blocks
    const int rB    = wn * 32 + ((lane >> 4) << 3) + (lane & 7);
    const uint32_t bXor = (uint32_t)((rB & 7) << 4);
    const int bkl   = ((lane >> 3) & 1) * 8;
    uint32_t bBase[2];
    #pragma unroll
    for (int nt2 = 0; nt2 < 2; nt2++) {
        int r = rB + nt2 * 16;
        bBase[nt2] = BsU + (uint32_t)((r >> 3) * 1024 + (r & 7) * 128);
    }

    #pragma unroll
    for (int s = 0; s < NSLICE; s++) {
        if (s == NSLICE - 1) { CP_ASYNC_WAIT(0); } else { CP_ASYNC_WAIT(1); }
        __syncthreads();
        if (s + 2 < NSLICE) {            // buffer (s+2)%3 == (s-1)%3 is free now
            ISSUE_A(s + 2, (s + 2) % 3);
            CP_ASYNC_COMMIT();
        }

        const uint32_t aStage = AsU + (uint32_t)((s % 3) * A_SLAB_BYTES);
        #pragma unroll
        for (int ks = 0; ks < 4; ks++) {
            const int kg = s * 4 + ks;
            uint32_t a[2][4];
            #pragma unroll
            for (int mt = 0; mt < 2; mt++) {
                uint32_t addr = aStage + aRowB + (uint32_t)(mt * 16 * 128)
                              + (uint32_t)(((akl + ks * 16) * 2) ^ aXor);
                ldm_x4(a[mt], addr);
            }
            uint32_t b[2][4];
            const uint32_t kOff = (uint32_t)((kg >> 2) * B_CHUNK_B)
                                + (uint32_t)((((kg & 3) * 16 + bkl) * 2) ^ bXor);
            #pragma unroll
            for (int nt2 = 0; nt2 < 2; nt2++)
                ldm_x4(b[nt2], bBase[nt2] + kOff);

            #pragma unroll
            for (int mt = 0; mt < 2; mt++)
                #pragma unroll
                for (int nt = 0; nt < 4; nt++)
                    mma16816(acc[mt][nt], a[mt], &b[nt >> 1][(nt & 1) * 2]);
        }
    }
    #undef ISSUE_A

    // ---- epilogue: direct fp32 stores ----
    const int g  = lane >> 2;
    const int tg = lane & 3;
    #pragma unroll
    for (int mt = 0; mt < 2; mt++) {
        #pragma unroll
        for (int nt = 0; nt < 4; nt++) {
            long row = arow0 + wm * 32 + mt * 16 + g;
            int  col = bn + wn * 32 + nt * 8 + tg * 2;
            float2 v0 = make_float2(acc[mt][nt][0], acc[mt][nt][1]);
            float2 v1 = make_float2(acc[mt][nt][2], acc[mt][nt][3]);
            *reinterpret_cast<float2*>(out + row * N_OUT + col)       = v0;
            *reinterpret_cast<float2*>(out + (row + 8) * N_OUT + col) = v1;
        }
    }
}

extern "C" void kernel_launch(void* const* d_in, const int* in_sizes, int n_in,
                              void* d_out, int out_size) {
    const float* h = (const float*)d_in[0];
    const float* W = (const float*)d_in[1];
    if (n_in >= 2 && in_sizes[0] < in_sizes[1]) {
        const float* t = h; h = W; W = t;
    }
    const int n_threads = M_TOTAL * K_DIM / 4 + 2 * B_IMG_HALVES;  // 1114112
    prep_kernel<<<(n_threads + 511) / 512, 512>>>(
        reinterpret_cast<const float4*>(h), W);

    cudaFuncSetAttribute(gat_gemm_kernel,
                         cudaFuncAttributeMaxDynamicSharedMemorySize, SMEM_BYTES);
    const int grid = (M_TOTAL / CTA_M) * (N_OUT / CTA_N);  // 256
    gat_gemm_kernel<<<grid, THREADS, SMEM_BYTES>>>((float*)d_out);
}

// round 11
// speedup vs baseline: 1.1174x; 1.1174x over previous
#include <cuda_runtime.h>
#include <cuda_fp16.h>
#include <cstdint>

// ============================================================================
// MultiHeadGraphAttentionLayer — reduced form.
// softmax rows sum to 1, so out = hp = h @ Wcat : [16384,256] x [256,256].
// Single GEMM kernel + tiny B-image prepass. A is fetched as RAW fp32 via
// cp.async (2 slices ahead) and converted fp32->fp16 one slice ahead of the
// MMA, by the same thread that fetched it (no extra barriers). B is a
// verbatim swizzled fp16 image. ldmatrix + mma.sync.m16n8k16. sm_103 base.
// ============================================================================

static constexpr int M_TOTAL = 16384;
static constexpr int N_OUT   = 256;
static constexpr int K_DIM   = 256;

static constexpr int CTA_M   = 128;
static constexpr int CTA_N   = 128;
static constexpr int THREADS = 256;

static constexpr int KSLAB   = 32;              // k-floats per slice
static constexpr int NSLICE  = K_DIM / KSLAB;   // 8

static constexpr int B_IMG_HALVES = CTA_N * K_DIM;          // 32768 (64 KB)
static constexpr int B_CHUNK_B    = 16384;                  // one k-group of 4 k16-steps
static constexpr int F_SLAB_B     = CTA_M * KSLAB * 4;      // 16384 fp32 slab
static constexpr int H_SLAB_B     = CTA_M * KSLAB * 2;      // 8192  fp16 slab
static constexpr int SMEM_BYTES   = B_IMG_HALVES * 2 + 2 * F_SLAB_B + 2 * H_SLAB_B; // 114688

// swizzled fp16 B images (128 KB) — static device scratch (no allocation)
__device__ __align__(16) __half g_bt[2 * B_IMG_HALVES];

__device__ __forceinline__ uint32_t smem_u32(const void* p) {
    uint32_t a;
    asm("{ .reg .u64 t; cvta.to.shared.u64 t, %1; cvt.u32.u64 %0, t; }"
        : "=r"(a) : "l"(p));
    return a;
}

__device__ __forceinline__ void ldm_x4(uint32_t* r, uint32_t addr) {
    asm volatile("ldmatrix.sync.aligned.m8n8.x4.shared.b16 {%0,%1,%2,%3}, [%4];"
                 : "=r"(r[0]), "=r"(r[1]), "=r"(r[2]), "=r"(r[3])
                 : "r"(addr));
}

__device__ __forceinline__ void mma16816(float* c, const uint32_t* a,
                                         const uint32_t* b) {
    asm volatile(
        "mma.sync.aligned.m16n8k16.row.col.f32.f16.f16.f32 "
        "{%0,%1,%2,%3}, {%4,%5,%6,%7}, {%8,%9}, {%0,%1,%2,%3};"
        : "+f"(c[0]), "+f"(c[1]), "+f"(c[2]), "+f"(c[3])
        : "r"(a[0]), "r"(a[1]), "r"(a[2]), "r"(a[3]), "r"(b[0]), "r"(b[1]));
}

__device__ __forceinline__ uint32_t pack_h2(float x, float y) {
    __half2 h = __floats2half2_rn(x, y);
    return *reinterpret_cast<uint32_t*>(&h);
}

#define CP_ASYNC_16(smem_addr, gptr)                                           \
    asm volatile("cp.async.cg.shared.global [%0], [%1], 16;"                   \
                 :: "r"(smem_addr), "l"(gptr))
#define CP_ASYNC_COMMIT() asm volatile("cp.async.commit_group;")
#define CP_ASYNC_WAIT(n)  asm volatile("cp.async.wait_group %0;" :: "n"(n))

// B image byte offset for local row c (0..127), col f (0..255)
__device__ __forceinline__ uint32_t b_img_off(int c, int f) {
    uint32_t off = (uint32_t)(((c >> 3) + (f >> 6) * 16) * 1024
                              + (c & 7) * 128 + (f & 63) * 2);
    return off ^ ((off >> 3) & 0x70);
}

// ---------------- prepass: B images only ----------------
__global__ __launch_bounds__(512)
void prep_b_kernel(const float* __restrict__ W) {
    int u = blockIdx.x * blockDim.x + threadIdx.x;   // 0..65535
    if (u < 2 * B_IMG_HALVES) {
        int img = u >> 15;
        int rem = u & 32767;
        int f   = rem >> 7;          // 0..255
        int c   = rem & 127;         // local col (consecutive -> coalesced d)
        int n   = img * 128 + c;
        int hh  = n >> 6;
        int d   = n & 63;
        float w = W[hh * 16384 + f * 64 + d];
        g_bt[img * B_IMG_HALVES + (b_img_off(c, f) >> 1)] = __float2half_rn(w);
    }
}

// ---------------- GEMM ----------------
__global__ __launch_bounds__(THREADS, 2)
void gat_gemm_kernel(const float* __restrict__ hin,
                     float* __restrict__ out) {
    extern __shared__ char smem[];
    char* Bs = smem;                              // 64 KB fp16 B image
    char* Fs = smem + B_IMG_HALVES * 2;           // 2 x 16 KB fp32 slabs
    char* Hs = Fs + 2 * F_SLAB_B;                 // 2 x  8 KB fp16 slabs

    const int tid  = threadIdx.x;
    const int wid  = tid >> 5;
    const int lane = tid & 31;

    const int bm   = blockIdx.x >> 1;
    const int img  = blockIdx.x & 1;
    const int bn   = img * CTA_N;
    const long arow0 = (long)bm * CTA_M;

    const float*  aGlob = hin + arow0 * K_DIM;
    const __half* bGlob = g_bt + img * B_IMG_HALVES;
    const uint32_t BsU = smem_u32(Bs);
    const uint32_t FsU = smem_u32(Fs);

    // fp32 slab fetch: 1024 16B chunks, 4/thread; chunk c -> row r=c>>3, q=c&7
    #define ISSUE_F(s, buf) do {                                               \
        const float* _src = aGlob + (s) * KSLAB;                               \
        _Pragma("unroll")                                                      \
        for (int i = 0; i < 4; i++) {                                          \
            int c = tid + i * THREADS;                                         \
            int r = c >> 3, q = c & 7;                                         \
            uint32_t dst = FsU + (uint32_t)((buf) * F_SLAB_B + r * 128 + q * 16); \
            CP_ASYNC_16(dst, _src + r * K_DIM + q * 4);                        \
        }                                                                      \
    } while (0)

    // convert this thread's own chunks: fp32 slab buf -> fp16 slab hbuf
    // fp16 dst: r*64 + (((q>>1)*16) ^ (((r>>1)&3)<<4)) + (q&1)*8
    #define CONVERT_F(buf, hbuf) do {                                          \
        _Pragma("unroll")                                                      \
        for (int i = 0; i < 4; i++) {                                          \
            int c = tid + i * THREADS;                                         \
            int r = c >> 3, q = c & 7;                                         \
            float4 v = *reinterpret_cast<const float4*>(                       \
                Fs + (buf) * F_SLAB_B + r * 128 + q * 16);                     \
            uint2 u;                                                           \
            u.x = pack_h2(v.x, v.y);                                           \
            u.y = pack_h2(v.z, v.w);                                           \
            uint32_t off = (uint32_t)(r * 64 + (((q >> 1) * 16)                \
                           ^ (((r >> 1) & 3) << 4)) + (q & 1) * 8);            \
            *reinterpret_cast<uint2*>(Hs + (hbuf) * H_SLAB_B + off) = u;       \
        }                                                                      \
    } while (0)

    // head: G0 = {B image, f0}; G1 = {f1}
    {
        #pragma unroll
        for (int i = 0; i < 16; i++) {
            int c = tid + i * THREADS;
            CP_ASYNC_16(BsU + (uint32_t)(c * 16), bGlob + c * 8);
        }
    }
    ISSUE_F(0, 0); CP_ASYNC_COMMIT();
    ISSUE_F(1, 1); CP_ASYNC_COMMIT();

    // ---- warp tiling: 8 warps = 4(m) x 2(n); warp tile 32(m) x 64(n) ----
    const int wm = wid & 3;
    const int wn = wid >> 2;

    float acc[2][8][4];
    #pragma unroll
    for (int mt = 0; mt < 2; mt++)
        #pragma unroll
        for (int nt = 0; nt < 8; nt++)
            #pragma unroll
            for (int q = 0; q < 4; q++) acc[mt][nt][q] = 0.f;

    // A lane addressing: 64B rows, verified ((r>>1)&3)<<4 swizzle
    const int lrl = lane & 15;
    const uint32_t aXor = (uint32_t)(((lrl >> 1) & 3) << 4);
    const uint32_t aRow = (uint32_t)((wm * 32 + lrl) * 64);
    const uint32_t aQ   = (uint32_t)((lane >> 4) * 16);
    const uint32_t HsU  = smem_u32(Hs);

    // B lane addressing (verified)
    const int rB    = wn * 64 + ((lane >> 4) << 3) + (lane & 7);
    const uint32_t bXor = (uint32_t)((rB & 7) << 4);
    const int bkl   = ((lane >> 3) & 1) * 8;
    uint32_t bBase[4];
    #pragma unroll
    for (int nt2 = 0; nt2 < 4; nt2++) {
        int r = rB + nt2 * 16;
        bBase[nt2] = BsU + (uint32_t)((r >> 3) * 1024 + (r & 7) * 128);
    }

    // pre-loop: convert f0 -> H0, start f2
    CP_ASYNC_WAIT(1);            // G0 {B, f0} complete
    CONVERT_F(0, 0);
    ISSUE_F(2, 0);               // f2 -> F0 (this thread already read its F0 data)
    CP_ASYNC_COMMIT();
    __syncthreads();             // H0 + B published

    #pragma unroll
    for (int s = 0; s < NSLICE; s++) {
        // convert next slice (overlaps with this slice's MMAs issue-wise)
        if (s + 1 < NSLICE) {
            if (s <= 5) { CP_ASYNC_WAIT(1); } else { CP_ASYNC_WAIT(0); }
            CONVERT_F((s + 1) & 1, (s + 1) & 1);
            if (s + 3 < NSLICE) { ISSUE_F(s + 3, (s + 3) & 1); CP_ASYNC_COMMIT(); }
        }

        const uint32_t hStage = HsU + (uint32_t)((s & 1) * H_SLAB_B);
        #pragma unroll
        for (int ks = 0; ks < 2; ks++) {
            const int kg = s * 2 + ks;
            uint32_t a[2][4];
            #pragma unroll
            for (int mt = 0; mt < 2; mt++) {
                uint32_t addr = hStage + aRow + (uint32_t)(mt * 16 * 64)
                              + (((uint32_t)(ks * 32) + aQ) ^ aXor);
                ldm_x4(a[mt], addr);
            }
            uint32_t b[4][4];
            const uint32_t kOff = (uint32_t)((kg >> 2) * B_CHUNK_B)
                                + (uint32_t)((((kg & 3) * 16 + bkl) * 2) ^ bXor);
            #pragma unroll
            for (int nt2 = 0; nt2 < 4; nt2++)
                ldm_x4(b[nt2], bBase[nt2] + kOff);

            #pragma unroll
            for (int mt = 0; mt < 2; mt++)
                #pragma unroll
                for (int nt = 0; nt < 8; nt++)
                    mma16816(acc[mt][nt], a[mt], &b[nt >> 1][(nt & 1) * 2]);
        }
        __syncthreads();   // publish H((s+1)&1); all warps done with H(s&1)
    }
    #undef ISSUE_F
    #undef CONVERT_F

    // ---- epilogue: direct fp32 stores ----
    const int g  = lane >> 2;
    const int tg = lane & 3;
    #pragma unroll
    for (int mt = 0; mt < 2; mt++) {
        #pragma unroll
        for (int nt = 0; nt < 8; nt++) {
            long row = arow0 + wm * 32 + mt * 16 + g;
            int  col = bn + wn * 64 + nt * 8 + tg * 2;
            float2 v0 = make_float2(acc[mt][nt][0], acc[mt][nt][1]);
            float2 v1 = make_float2(acc[mt][nt][2], acc[mt][nt][3]);
            *reinterpret_cast<float2*>(out + row * N_OUT + col)       = v0;
            *reinterpret_cast<float2*>(out + (row + 8) * N_OUT + col) = v1;
        }
    }
}

extern "C" void kernel_launch(void* const* d_in, const int* in_sizes, int n_in,
                              void* d_out, int out_size) {
    const float* h = (const float*)d_in[0];
    const float* W = (const float*)d_in[1];
    if (n_in >= 2 && in_sizes[0] < in_sizes[1]) {
        const float* t = h; h = W; W = t;
    }
    prep_b_kernel<<<(2 * B_IMG_HALVES + 511) / 512, 512>>>(W);

    cudaFuncSetAttribute(gat_gemm_kernel,
                         cudaFuncAttributeMaxDynamicSharedMemorySize, SMEM_BYTES);
    const int grid = (M_TOTAL / CTA_M) * (N_OUT / CTA_N);  // 256
    gat_gemm_kernel<<<grid, THREADS, SMEM_BYTES>>>(h, (float*)d_out);
}

// round 12
// speedup vs baseline: 1.1412x; 1.0213x over previous
#include <cuda_runtime.h>
#include <cuda_fp16.h>
#include <cstdint>

// ============================================================================
// MultiHeadGraphAttentionLayer — reduced form.
// softmax rows sum to 1, so out = hp = h @ Wcat : [16384,256] x [256,256].
// prep_b (tiny) builds swizzled fp16 B images; GEMM is launched with
// PROGRAMMATIC STREAM SERIALIZATION (PDL) so its A-slab prologue overlaps
// prep + launch latency; cudaGridDependencySynchronize() guards only the
// B-image copy. A fetched as raw fp32 cp.async, converted one slice ahead.
// ldmatrix + mma.sync.m16n8k16. sm_103 base ISA only.
// ============================================================================

static constexpr int M_TOTAL = 16384;
static constexpr int N_OUT   = 256;
static constexpr int K_DIM   = 256;

static constexpr int CTA_M   = 128;
static constexpr int CTA_N   = 128;
static constexpr int THREADS = 256;

static constexpr int KSLAB   = 32;              // k-floats per slice
static constexpr int NSLICE  = K_DIM / KSLAB;   // 8

static constexpr int B_IMG_HALVES = CTA_N * K_DIM;          // 32768 (64 KB)
static constexpr int B_CHUNK_B    = 16384;                  // one k-group of 4 k16-steps
static constexpr int F_SLAB_B     = CTA_M * KSLAB * 4;      // 16384 fp32 slab
static constexpr int H_SLAB_B     = CTA_M * KSLAB * 2;      // 8192  fp16 slab
static constexpr int SMEM_BYTES   = B_IMG_HALVES * 2 + 2 * F_SLAB_B + 2 * H_SLAB_B; // 114688

// swizzled fp16 B images (128 KB) — static device scratch (no allocation)
__device__ __align__(16) __half g_bt[2 * B_IMG_HALVES];

__device__ __forceinline__ uint32_t smem_u32(const void* p) {
    uint32_t a;
    asm("{ .reg .u64 t; cvta.to.shared.u64 t, %1; cvt.u32.u64 %0, t; }"
        : "=r"(a) : "l"(p));
    return a;
}

__device__ __forceinline__ void ldm_x4(uint32_t* r, uint32_t addr) {
    asm volatile("ldmatrix.sync.aligned.m8n8.x4.shared.b16 {%0,%1,%2,%3}, [%4];"
                 : "=r"(r[0]), "=r"(r[1]), "=r"(r[2]), "=r"(r[3])
                 : "r"(addr));
}

__device__ __forceinline__ void mma16816(float* c, const uint32_t* a,
                                         const uint32_t* b) {
    asm volatile(
        "mma.sync.aligned.m16n8k16.row.col.f32.f16.f16.f32 "
        "{%0,%1,%2,%3}, {%4,%5,%6,%7}, {%8,%9}, {%0,%1,%2,%3};"
        : "+f"(c[0]), "+f"(c[1]), "+f"(c[2]), "+f"(c[3])
        : "r"(a[0]), "r"(a[1]), "r"(a[2]), "r"(a[3]), "r"(b[0]), "r"(b[1]));
}

__device__ __forceinline__ uint32_t pack_h2(float x, float y) {
    __half2 h = __floats2half2_rn(x, y);
    return *reinterpret_cast<uint32_t*>(&h);
}

#define CP_ASYNC_16(smem_addr, gptr)                                           \
    asm volatile("cp.async.cg.shared.global [%0], [%1], 16;"                   \
                 :: "r"(smem_addr), "l"(gptr))
#define CP_ASYNC_COMMIT() asm volatile("cp.async.commit_group;")
#define CP_ASYNC_WAIT(n)  asm volatile("cp.async.wait_group %0;" :: "n"(n))

// B image byte offset for local row c (0..127), col f (0..255)
__device__ __forceinline__ uint32_t b_img_off(int c, int f) {
    uint32_t off = (uint32_t)(((c >> 3) + (f >> 6) * 16) * 1024
                              + (c & 7) * 128 + (f & 63) * 2);
    return off ^ ((off >> 3) & 0x70);
}

// ---------------- prepass: B images only (triggers PDL early) ----------------
__global__ __launch_bounds__(512)
void prep_b_kernel(const float* __restrict__ W) {
    int u = blockIdx.x * blockDim.x + threadIdx.x;   // 0..65535
    if (u < 2 * B_IMG_HALVES) {
        int img = u >> 15;
        int rem = u & 32767;
        int f   = rem >> 7;          // 0..255
        int c   = rem & 127;         // local col (consecutive -> coalesced d)
        int n   = img * 128 + c;
        int hh  = n >> 6;
        int d   = n & 63;
        float w = W[hh * 16384 + f * 64 + d];
        g_bt[img * B_IMG_HALVES + (b_img_off(c, f) >> 1)] = __float2half_rn(w);
    }
    cudaTriggerProgrammaticLaunchCompletion();
}

// ---------------- GEMM (PDL secondary) ----------------
__global__ __launch_bounds__(THREADS, 2)
void gat_gemm_kernel(const float* __restrict__ hin,
                     float* __restrict__ out) {
    extern __shared__ char smem[];
    char* Bs = smem;                              // 64 KB fp16 B image
    char* Fs = smem + B_IMG_HALVES * 2;           // 2 x 16 KB fp32 slabs
    char* Hs = Fs + 2 * F_SLAB_B;                 // 2 x  8 KB fp16 slabs

    const int tid  = threadIdx.x;
    const int wid  = tid >> 5;
    const int lane = tid & 31;

    const int bm   = blockIdx.x >> 1;
    const int img  = blockIdx.x & 1;
    const int bn   = img * CTA_N;
    const long arow0 = (long)bm * CTA_M;

    const float*  aGlob = hin + arow0 * K_DIM;
    const __half* bGlob = g_bt + img * B_IMG_HALVES;
    const uint32_t BsU = smem_u32(Bs);
    const uint32_t FsU = smem_u32(Fs);

    // fp32 slab fetch: 1024 16B chunks, 4/thread; chunk c -> row r=c>>3, q=c&7
    #define ISSUE_F(s, buf) do {                                               \
        const float* _src = aGlob + (s) * KSLAB;                               \
        _Pragma("unroll")                                                      \
        for (int i = 0; i < 4; i++) {                                          \
            int c = tid + i * THREADS;                                         \
            int r = c >> 3, q = c & 7;                                         \
            uint32_t dst = FsU + (uint32_t)((buf) * F_SLAB_B + r * 128 + q * 16); \
            CP_ASYNC_16(dst, _src + r * K_DIM + q * 4);                        \
        }                                                                      \
    } while (0)

    // convert this thread's own chunks: fp32 slab buf -> fp16 slab hbuf
    #define CONVERT_F(buf, hbuf) do {                                          \
        _Pragma("unroll")                                                      \
        for (int i = 0; i < 4; i++) {                                          \
            int c = tid + i * THREADS;                                         \
            int r = c >> 3, q = c & 7;                                         \
            float4 v = *reinterpret_cast<const float4*>(                       \
                Fs + (buf) * F_SLAB_B + r * 128 + q * 16);                     \
            uint2 u;                                                           \
            u.x = pack_h2(v.x, v.y);                                           \
            u.y = pack_h2(v.z, v.w);                                           \
            uint32_t off = (uint32_t)(r * 64 + (((q >> 1) * 16)                \
                           ^ (((r >> 1) & 3) << 4)) + (q & 1) * 8);            \
            *reinterpret_cast<uint2*>(Hs + (hbuf) * H_SLAB_B + off) = u;       \
        }                                                                      \
    } while (0)

    // head (runs concurrently with prep under PDL — touches only h):
    // G0 = {f0}, G1 = {f1}
    ISSUE_F(0, 0); CP_ASYNC_COMMIT();
    ISSUE_F(1, 1); CP_ASYNC_COMMIT();

    // wait for prep's g_bt, then B image copy: G2 = {B}
    cudaGridDependencySynchronize();
    {
        #pragma unroll
        for (int i = 0; i < 16; i++) {
            int c = tid + i * THREADS;
            CP_ASYNC_16(BsU + (uint32_t)(c * 16), bGlob + c * 8);
        }
    }
    CP_ASYNC_COMMIT();

    // ---- warp tiling: 8 warps = 4(m) x 2(n); warp tile 32(m) x 64(n) ----
    const int wm = wid & 3;
    const int wn = wid >> 2;

    float acc[2][8][4];
    #pragma unroll
    for (int mt = 0; mt < 2; mt++)
        #pragma unroll
        for (int nt = 0; nt < 8; nt++)
            #pragma unroll
            for (int q = 0; q < 4; q++) acc[mt][nt][q] = 0.f;

    // A lane addressing: 64B rows, verified ((r>>1)&3)<<4 swizzle
    const int lrl = lane & 15;
    const uint32_t aXor = (uint32_t)(((lrl >> 1) & 3) << 4);
    const uint32_t aRow = (uint32_t)((wm * 32 + lrl) * 64);
    const uint32_t aQ   = (uint32_t)((lane >> 4) * 16);
    const uint32_t HsU  = smem_u32(Hs);

    // B lane addressing (verified)
    const int rB    = wn * 64 + ((lane >> 4) << 3) + (lane & 7);
    const uint32_t bXor = (uint32_t)((rB & 7) << 4);
    const int bkl   = ((lane >> 3) & 1) * 8;
    uint32_t bBase[4];
    #pragma unroll
    for (int nt2 = 0; nt2 < 4; nt2++) {
        int r = rB + nt2 * 16;
        bBase[nt2] = BsU + (uint32_t)((r >> 3) * 1024 + (r & 7) * 128);
    }

    // pre-loop: f0 done -> convert to H0; issue f2 (G3); ensure B done
    CP_ASYNC_WAIT(2);            // G0 {f0} complete (G1, G2 may pend)
    CONVERT_F(0, 0);
    ISSUE_F(2, 0);               // f2 -> F0 (this thread already read its F0 data)
    CP_ASYNC_COMMIT();           // G3
    CP_ASYNC_WAIT(1);            // G0..G2 done => B image + f1 resident
    __syncthreads();             // H0 + B published

    // groups: f0=G0, f1=G1, B=G2, f(k)=G(k+1) for k>=2
    #pragma unroll
    for (int s = 0; s < NSLICE; s++) {
        // convert next slice (overlaps with this slice's MMAs issue-wise)
        if (s + 1 < NSLICE) {
            if (s <= 5) { CP_ASYNC_WAIT(1); } else { CP_ASYNC_WAIT(0); }
            CONVERT_F((s + 1) & 1, (s + 1) & 1);
            if (s + 3 < NSLICE) { ISSUE_F(s + 3, (s + 3) & 1); CP_ASYNC_COMMIT(); }
        }

        const uint32_t hStage = HsU + (uint32_t)((s & 1) * H_SLAB_B);
        #pragma unroll
        for (int ks = 0; ks < 2; ks++) {
            const int kg = s * 2 + ks;
            uint32_t a[2][4];
            #pragma unroll
            for (int mt = 0; mt < 2; mt++) {
                uint32_t addr = hStage + aRow + (uint32_t)(mt * 16 * 64)
                              + (((uint32_t)(ks * 32) + aQ) ^ aXor);
                ldm_x4(a[mt], addr);
            }
            uint32_t b[4][4];
            const uint32_t kOff = (uint32_t)((kg >> 2) * B_CHUNK_B)
                                + (uint32_t)((((kg & 3) * 16 + bkl) * 2) ^ bXor);
            #pragma unroll
            for (int nt2 = 0; nt2 < 4; nt2++)
                ldm_x4(b[nt2], bBase[nt2] + kOff);

            #pragma unroll
            for (int mt = 0; mt < 2; mt++)
                #pragma unroll
                for (int nt = 0; nt < 8; nt++)
                    mma16816(acc[mt][nt], a[mt], &b[nt >> 1][(nt & 1) * 2]);
        }
        __syncthreads();   // publish H((s+1)&1); all warps done with H(s&1)
    }
    #undef ISSUE_F
    #undef CONVERT_F

    // ---- epilogue: direct fp32 stores ----
    const int g  = lane >> 2;
    const int tg = lane & 3;
    #pragma unroll
    for (int mt = 0; mt < 2; mt++) {
        #pragma unroll
        for (int nt = 0; nt < 8; nt++) {
            long row = arow0 + wm * 32 + mt * 16 + g;
            int  col = bn + wn * 64 + nt * 8 + tg * 2;
            float2 v0 = make_float2(acc[mt][nt][0], acc[mt][nt][1]);
            float2 v1 = make_float2(acc[mt][nt][2], acc[mt][nt][3]);
            *reinterpret_cast<float2*>(out + row * N_OUT + col)       = v0;
            *reinterpret_cast<float2*>(out + (row + 8) * N_OUT + col) = v1;
        }
    }
}

extern "C" void kernel_launch(void* const* d_in, const int* in_sizes, int n_in,
                              void* d_out, int out_size) {
    const float* h = (const float*)d_in[0];
    const float* W = (const float*)d_in[1];
    if (n_in >= 2 && in_sizes[0] < in_sizes[1]) {
        const float* t = h; h = W; W = t;
    }
    prep_b_kernel<<<(2 * B_IMG_HALVES + 511) / 512, 512>>>(W);

    cudaFuncSetAttribute(gat_gemm_kernel,
                         cudaFuncAttributeMaxDynamicSharedMemorySize, SMEM_BYTES);

    // PDL: GEMM overlaps prep; the device-side griddepsync guards g_bt reads.
    cudaLaunchConfig_t cfg = {};
    cfg.gridDim  = dim3((M_TOTAL / CTA_M) * (N_OUT / CTA_N), 1, 1);  // 256
    cfg.blockDim = dim3(THREADS, 1, 1);
    cfg.dynamicSmemBytes = SMEM_BYTES;
    cudaLaunchAttribute attrs[1];
    attrs[0].id = cudaLaunchAttributeProgrammaticStreamSerialization;
    attrs[0].val.programmaticStreamSerializationAllowed = 1;
    cfg.attrs = attrs;
    cfg.numAttrs = 1;
    cudaLaunchKernelEx(&cfg, gat_gemm_kernel, h, (float*)d_out);
}